// round 5
// baseline (speedup 1.0000x reference)
#include <cuda_runtime.h>
#include <cstdint>

#define B_     64
#define N_     256
#define INDIM  512
#define OUTDIM 512
#define KSLOT  8
#define DKDIM  64

// Scratch: H^T [b][feature][m]
__device__ float g_ht[(size_t)B_ * OUTDIM * N_];

// ---------------------------------------------------------------------------
__device__ __forceinline__ uint32_t tf32u(float x) {
    uint32_t r; asm("cvt.rna.tf32.f32 %0, %1;" : "=r"(r) : "f"(x)); return r;
}

__device__ __forceinline__ void mma_tf32(float c[4], const uint32_t a[4], const uint32_t b[2]) {
    asm volatile(
        "mma.sync.aligned.m16n8k8.row.col.f32.tf32.tf32.f32 "
        "{%0,%1,%2,%3}, {%4,%5,%6,%7}, {%8,%9}, {%0,%1,%2,%3};"
        : "+f"(c[0]), "+f"(c[1]), "+f"(c[2]), "+f"(c[3])
        : "r"(a[0]), "r"(a[1]), "r"(a[2]), "r"(a[3]), "r"(b[0]), "r"(b[1]));
}

// Permuted k-layout within a 32-wide chunk row:
//   element k (0..31) stored at float column (k>>3)*8 + (k&3)*2 + ((k&7)>>2)
// so (k, k+4) are adjacent -> one LDS.64 per fragment pair.
// Row pitch 36 floats (144B) -> fragment LDS.64 is exactly 2-phase.
#define PITCH 36

// ---------------------------------------------------------------------------
// Stage 1: HT[b][f][m] = relu( X @ W + bias )
// CTA 128(m) x 128(f), 8 warps (4 m x 2 f), warp tile 32x64. K chunks of 32.
// Double-buffered smem: buffer = 256 rows (A: 0..127, B: 128..255) x PITCH.
// W is loaded k-major directly (transpose folded into the STS scatter).
// ---------------------------------------------------------------------------
#define S1_DYN (2 * 256 * PITCH * 4)
__global__ __launch_bounds__(256) void s1_linear_mma(
    const float* __restrict__ X, const float* __restrict__ W,
    const float* __restrict__ bias, float* __restrict__ HT)
{
    extern __shared__ uint32_t sm1[];

    const int tid = threadIdx.x;
    const int warpId = tid >> 5, lid = tid & 31;
    const int gid = lid >> 2, tig = lid & 3;
    const int wr = warpId & 3;            // m: 4 warps * 32
    const int wc = warpId >> 2;           // f: 2 warps * 64
    const int mBase = blockIdx.y * 128;
    const int nBase = blockIdx.x * 128;

    float c[2][8][4];
    #pragma unroll
    for (int mt = 0; mt < 2; mt++)
        #pragma unroll
        for (int nt = 0; nt < 8; nt++)
            #pragma unroll
            for (int i = 0; i < 4; i++) c[mt][nt][i] = 0.0f;

    float4 ar[4], br[4];

    // A tile: 128 rows(m) x 32(k) = 1024 float4; idx=tid+it*256, r=idx>>3, c4=idx&7
    auto loadA = [&](int k0) {
        #pragma unroll
        for (int it = 0; it < 4; it++) {
            int idx = tid + it * 256;
            int r = idx >> 3, c4 = idx & 7;
            ar[it] = *reinterpret_cast<const float4*>(X + (size_t)(mBase + r) * INDIM + k0 + c4 * 4);
        }
    };
    // W tile (k-major): 32 rows(k) x 128(n) = 1024 float4; kr=idx>>5, c4=idx&31
    auto loadBW = [&](int k0) {
        #pragma unroll
        for (int it = 0; it < 4; it++) {
            int idx = tid + it * 256;
            int kr = idx >> 5, c4 = idx & 31;
            br[it] = *reinterpret_cast<const float4*>(W + (size_t)(k0 + kr) * OUTDIM + nBase + c4 * 4);
        }
    };
    auto stsAll = [&](int buf) {
        uint32_t* base = sm1 + buf * (256 * PITCH);
        // A: thread holds 4 consecutive k at fixed row
        #pragma unroll
        for (int it = 0; it < 4; it++) {
            int idx = tid + it * 256;
            int r = idx >> 3, c4 = idx & 7;
            int ks = c4 >> 1, h = c4 & 1;
            uint32_t* s = base + r * PITCH + ks * 8 + h;
            s[0] = tf32u(ar[it].x); s[2] = tf32u(ar[it].y);
            s[4] = tf32u(ar[it].z); s[6] = tf32u(ar[it].w);
        }
        // B: thread holds 4 consecutive n at fixed k -> scatter to 4 rows, 1 perm col
        #pragma unroll
        for (int it = 0; it < 4; it++) {
            int idx = tid + it * 256;
            int kr = idx >> 5, c4 = idx & 31;
            int pc = (kr >> 3) * 8 + (kr & 3) * 2 + ((kr & 7) >> 2);
            uint32_t* s = base + (128 + c4 * 4) * PITCH + pc;
            s[0]         = tf32u(br[it].x);
            s[PITCH]     = tf32u(br[it].y);
            s[2 * PITCH] = tf32u(br[it].z);
            s[3 * PITCH] = tf32u(br[it].w);
        }
    };

    loadA(0); loadBW(0);
    stsAll(0);
    __syncthreads();

    for (int cc = 0; cc < INDIM / 32; cc++) {
        const int cur = cc & 1;
        const bool hasNext = (cc + 1 < INDIM / 32);
        if (hasNext) { loadA((cc + 1) * 32); loadBW((cc + 1) * 32); }

        const uint32_t* base = sm1 + cur * (256 * PITCH);
        #pragma unroll
        for (int ks = 0; ks < 4; ks++) {
            uint32_t bfr[8][2];
            #pragma unroll
            for (int nt = 0; nt < 8; nt++) {
                uint2 t = *reinterpret_cast<const uint2*>(
                    base + (128 + wc * 64 + nt * 8 + gid) * PITCH + ks * 8 + tig * 2);
                bfr[nt][0] = t.x; bfr[nt][1] = t.y;
            }
            uint32_t afr[2][4];
            #pragma unroll
            for (int mt = 0; mt < 2; mt++) {
                int r0 = wr * 32 + mt * 16 + gid;
                uint2 t0 = *reinterpret_cast<const uint2*>(base + r0 * PITCH + ks * 8 + tig * 2);
                uint2 t1 = *reinterpret_cast<const uint2*>(base + (r0 + 8) * PITCH + ks * 8 + tig * 2);
                afr[mt][0] = t0.x; afr[mt][2] = t0.y;
                afr[mt][1] = t1.x; afr[mt][3] = t1.y;
            }
            #pragma unroll
            for (int mt = 0; mt < 2; mt++)
                #pragma unroll
                for (int nt = 0; nt < 8; nt++)
                    mma_tf32(c[mt][nt], afr[mt], bfr[nt]);
        }
        if (hasNext) {
            stsAll(cur ^ 1);
            __syncthreads();
        }
    }

    // Epilogue: bias + relu, write transposed HT[b][f][m]
    const int batch = mBase >> 8;                 // 128-tile never straddles batch
    float* dst = HT + (size_t)batch * OUTDIM * N_;
    const int mloc = (mBase & 255) + wr * 32;
    #pragma unroll
    for (int mt = 0; mt < 2; mt++) {
        int m0 = mloc + mt * 16 + gid;
        #pragma unroll
        for (int nt = 0; nt < 8; nt++) {
            int f0 = nBase + wc * 64 + nt * 8 + tig * 2;
            float b0 = bias[f0], b1 = bias[f0 + 1];
            dst[(size_t)f0 * N_ + m0]           = fmaxf(c[mt][nt][0] + b0, 0.0f);
            dst[(size_t)(f0 + 1) * N_ + m0]     = fmaxf(c[mt][nt][1] + b1, 0.0f);
            dst[(size_t)f0 * N_ + m0 + 8]       = fmaxf(c[mt][nt][2] + b0, 0.0f);
            dst[(size_t)(f0 + 1) * N_ + m0 + 8] = fmaxf(c[mt][nt][3] + b1, 0.0f);
        }
    }
}

// ---------------------------------------------------------------------------
// Stage 2: out[b,n,k*64+d] = sum_m adj[b,k,n,m] * HT[b][k*64+d][m]
// CTA 128(n) x 64(d), 8 warps (4 n x 2 d), warp tile 32x32. m chunks of 32.
// Double-buffered smem: buffer = 192 rows (A: 0..127, B: 128..191) x PITCH.
// ---------------------------------------------------------------------------
#define S2_DYN (2 * 192 * PITCH * 4)
__global__ __launch_bounds__(256) void s2_aggregate_mma(
    const float* __restrict__ adj, const float* __restrict__ HT,
    float* __restrict__ out)
{
    extern __shared__ uint32_t sm2[];

    const int tid = threadIdx.x;
    const int warpId = tid >> 5, lid = tid & 31;
    const int gid = lid >> 2, tig = lid & 3;
    const int wr = warpId & 3;            // n: 4 warps * 32
    const int wc = warpId >> 2;           // d: 2 warps * 32
    const int nBase = blockIdx.x * 128;
    const int kslot = blockIdx.y;
    const int bIdx  = blockIdx.z;

    const float* A  = adj + (size_t)(bIdx * KSLOT + kslot) * N_ * N_;
    const float* Bp = HT + ((size_t)bIdx * OUTDIM + kslot * DKDIM) * N_;

    float c[2][4][4];
    #pragma unroll
    for (int mt = 0; mt < 2; mt++)
        #pragma unroll
        for (int nt = 0; nt < 4; nt++)
            #pragma unroll
            for (int i = 0; i < 4; i++) c[mt][nt][i] = 0.0f;

    float4 ar[4], br[2];

    auto loadA = [&](int m0) {
        #pragma unroll
        for (int it = 0; it < 4; it++) {
            int idx = tid + it * 256;
            int r = idx >> 3, c4 = idx & 7;
            ar[it] = *reinterpret_cast<const float4*>(A + (size_t)(nBase + r) * N_ + m0 + c4 * 4);
        }
    };
    auto loadB = [&](int m0) {
        #pragma unroll
        for (int it = 0; it < 2; it++) {
            int idx = tid + it * 256;
            int r = idx >> 3, c4 = idx & 7;
            br[it] = *reinterpret_cast<const float4*>(Bp + (size_t)r * N_ + m0 + c4 * 4);
        }
    };
    auto stsAll = [&](int buf) {
        uint32_t* base = sm2 + buf * (192 * PITCH);
        #pragma unroll
        for (int it = 0; it < 4; it++) {
            int idx = tid + it * 256;
            int r = idx >> 3, c4 = idx & 7;
            int ks = c4 >> 1, h = c4 & 1;
            uint32_t* s = base + r * PITCH + ks * 8 + h;
            s[0] = tf32u(ar[it].x); s[2] = tf32u(ar[it].y);
            s[4] = tf32u(ar[it].z); s[6] = tf32u(ar[it].w);
        }
        #pragma unroll
        for (int it = 0; it < 2; it++) {
            int idx = tid + it * 256;
            int r = idx >> 3, c4 = idx & 7;
            int ks = c4 >> 1, h = c4 & 1;
            uint32_t* s = base + (128 + r) * PITCH + ks * 8 + h;
            s[0] = tf32u(br[it].x); s[2] = tf32u(br[it].y);
            s[4] = tf32u(br[it].z); s[6] = tf32u(br[it].w);
        }
    };

    loadA(0); loadB(0);
    stsAll(0);
    __syncthreads();

    for (int cc = 0; cc < N_ / 32; cc++) {
        const int cur = cc & 1;
        const bool hasNext = (cc + 1 < N_ / 32);
        if (hasNext) { loadA((cc + 1) * 32); loadB((cc + 1) * 32); }

        const uint32_t* base = sm2 + cur * (192 * PITCH);
        #pragma unroll
        for (int ks = 0; ks < 4; ks++) {
            uint32_t bfr[4][2];
            #pragma unroll
            for (int nt = 0; nt < 4; nt++) {
                uint2 t = *reinterpret_cast<const uint2*>(
                    base + (128 + wc * 32 + nt * 8 + gid) * PITCH + ks * 8 + tig * 2);
                bfr[nt][0] = t.x; bfr[nt][1] = t.y;
            }
            uint32_t afr[2][4];
            #pragma unroll
            for (int mt = 0; mt < 2; mt++) {
                int r0 = wr * 32 + mt * 16 + gid;
                uint2 t0 = *reinterpret_cast<const uint2*>(base + r0 * PITCH + ks * 8 + tig * 2);
                uint2 t1 = *reinterpret_cast<const uint2*>(base + (r0 + 8) * PITCH + ks * 8 + tig * 2);
                afr[mt][0] = t0.x; afr[mt][2] = t0.y;
                afr[mt][1] = t1.x; afr[mt][3] = t1.y;
            }
            #pragma unroll
            for (int mt = 0; mt < 2; mt++)
                #pragma unroll
                for (int nt = 0; nt < 4; nt++)
                    mma_tf32(c[mt][nt], afr[mt], bfr[nt]);
        }
        if (hasNext) {
            stsAll(cur ^ 1);
            __syncthreads();
        }
    }

    // Epilogue: out[b][n][kslot*64 + d]
    float* dst = out + (size_t)bIdx * N_ * OUTDIM + kslot * DKDIM;
    #pragma unroll
    for (int mt = 0; mt < 2; mt++) {
        int n0 = nBase + wr * 32 + mt * 16 + gid;
        #pragma unroll
        for (int nt = 0; nt < 4; nt++) {
            int d0 = wc * 32 + nt * 8 + tig * 2;
            float2 v0 = make_float2(c[mt][nt][0], c[mt][nt][1]);
            float2 v1 = make_float2(c[mt][nt][2], c[mt][nt][3]);
            *reinterpret_cast<float2*>(dst + (size_t)n0 * OUTDIM + d0)       = v0;
            *reinterpret_cast<float2*>(dst + (size_t)(n0 + 8) * OUTDIM + d0) = v1;
        }
    }
}

// ---------------------------------------------------------------------------
extern "C" void kernel_launch(void* const* d_in, const int* in_sizes, int n_in,
                              void* d_out, int out_size)
{
    const float* node_feats = (const float*)d_in[0];  // (64,256,512)
    const float* adj        = (const float*)d_in[1];  // (64,8,256,256)
    const float* weight     = (const float*)d_in[2];  // (512,512)
    const float* bias       = (const float*)d_in[3];  // (512,)
    float* out = (float*)d_out;

    float* HT;
    cudaGetSymbolAddress((void**)&HT, g_ht);

    cudaFuncSetAttribute(s1_linear_mma, cudaFuncAttributeMaxDynamicSharedMemorySize, S1_DYN);
    cudaFuncSetAttribute(s2_aggregate_mma, cudaFuncAttributeMaxDynamicSharedMemorySize, S2_DYN);

    s1_linear_mma<<<dim3(OUTDIM / 128, (B_ * N_) / 128), 256, S1_DYN>>>(node_feats, weight, bias, HT);
    s2_aggregate_mma<<<dim3(N_ / 128, KSLOT, B_), 256, S2_DYN>>>(adj, HT, out);
}

// round 6
// speedup vs baseline: 1.2617x; 1.2617x over previous
#include <cuda_runtime.h>
#include <cstdint>

#define B_     64
#define N_     256
#define INDIM  512
#define OUTDIM 512
#define KSLOT  8
#define DKDIM  64

// Scratch: H^T [b][feature][m] and W^T [out][in]
__device__ float g_ht[(size_t)B_ * OUTDIM * N_];
__device__ float g_wt[OUTDIM * INDIM];

// ---------------------------------------------------------------------------
__device__ __forceinline__ uint32_t tf32u(float x) {
    uint32_t r; asm("cvt.rna.tf32.f32 %0, %1;" : "=r"(r) : "f"(x)); return r;
}

__device__ __forceinline__ void mma_tf32(float c[4], const uint32_t a[4], const uint32_t b[2]) {
    asm volatile(
        "mma.sync.aligned.m16n8k8.row.col.f32.tf32.tf32.f32 "
        "{%0,%1,%2,%3}, {%4,%5,%6,%7}, {%8,%9}, {%0,%1,%2,%3};"
        : "+f"(c[0]), "+f"(c[1]), "+f"(c[2]), "+f"(c[3])
        : "r"(a[0]), "r"(a[1]), "r"(a[2]), "r"(a[3]), "r"(b[0]), "r"(b[1]));
}

// Permuted k-layout within a 32-wide chunk row:
//   element k (0..31) stored at float column (k>>3)*8 + (k&3)*2 + ((k&7)>>2)
// so (k, k+4) are adjacent -> one LDS.64 per fragment pair.
// Row pitch 36 floats (144B) -> fragment LDS.64 is exactly 2-phase.
#define PITCH 36

// ---------------------------------------------------------------------------
// Kernel 0: W^T  (Wt[n][k] = W[k][n])
// ---------------------------------------------------------------------------
__global__ __launch_bounds__(256) void wt_kernel(const float* __restrict__ W,
                                                 float* __restrict__ Wt) {
    __shared__ float t[32][33];
    const int bx = blockIdx.x * 32;   // out (n)
    const int by = blockIdx.y * 32;   // in  (k)
    #pragma unroll
    for (int i = 0; i < 4; i++)
        t[threadIdx.y + i * 8][threadIdx.x] = W[(size_t)(by + threadIdx.y + i * 8) * OUTDIM + bx + threadIdx.x];
    __syncthreads();
    #pragma unroll
    for (int i = 0; i < 4; i++)
        Wt[(size_t)(bx + threadIdx.y + i * 8) * INDIM + by + threadIdx.x] = t[threadIdx.x][threadIdx.y + i * 8];
}

// ---------------------------------------------------------------------------
// Stage 1: HT[b][f][m] = relu( X @ W + bias )
// CTA 128(m) x 64(f), 8 warps (4 m x 2 f), warp tile 32x32. K chunks of 32.
// Grid = (8 f-tiles, 128 m-tiles) = 1024 CTAs. Double-buffered smem:
// buffer = 192 rows (A/m: 0..127, B/f: 128..191) x PITCH.
// ---------------------------------------------------------------------------
#define S1_DYN (2 * 192 * PITCH * 4)
__global__ __launch_bounds__(256) void s1_linear_mma(
    const float* __restrict__ X, const float* __restrict__ Wt,
    const float* __restrict__ bias, float* __restrict__ HT)
{
    extern __shared__ uint32_t sm1[];

    const int tid = threadIdx.x;
    const int warpId = tid >> 5, lid = tid & 31;
    const int gid = lid >> 2, tig = lid & 3;
    const int wr = warpId & 3;            // m: 4 warps * 32
    const int wc = warpId >> 2;           // f: 2 warps * 32
    const int mBase = blockIdx.y * 128;
    const int fBase = blockIdx.x * 64;

    float c[2][4][4];
    #pragma unroll
    for (int mt = 0; mt < 2; mt++)
        #pragma unroll
        for (int nt = 0; nt < 4; nt++)
            #pragma unroll
            for (int i = 0; i < 4; i++) c[mt][nt][i] = 0.0f;

    float4 ar[4], br[2];

    // A tile: 128 rows(m) x 32(k) = 1024 float4; idx=tid+it*256, r=idx>>3, c4=idx&7
    auto loadA = [&](int k0) {
        #pragma unroll
        for (int it = 0; it < 4; it++) {
            int idx = tid + it * 256;
            int r = idx >> 3, c4 = idx & 7;
            ar[it] = *reinterpret_cast<const float4*>(X + (size_t)(mBase + r) * INDIM + k0 + c4 * 4);
        }
    };
    // B tile: 64 rows(f) x 32(k) = 512 float4
    auto loadB = [&](int k0) {
        #pragma unroll
        for (int it = 0; it < 2; it++) {
            int idx = tid + it * 256;
            int r = idx >> 3, c4 = idx & 7;
            br[it] = *reinterpret_cast<const float4*>(Wt + (size_t)(fBase + r) * INDIM + k0 + c4 * 4);
        }
    };
    auto stsAll = [&](int buf) {
        uint32_t* base = sm1 + buf * (192 * PITCH);
        #pragma unroll
        for (int it = 0; it < 4; it++) {
            int idx = tid + it * 256;
            int r = idx >> 3, c4 = idx & 7;
            int ks = c4 >> 1, h = c4 & 1;
            uint32_t* s = base + r * PITCH + ks * 8 + h;
            s[0] = tf32u(ar[it].x); s[2] = tf32u(ar[it].y);
            s[4] = tf32u(ar[it].z); s[6] = tf32u(ar[it].w);
        }
        #pragma unroll
        for (int it = 0; it < 2; it++) {
            int idx = tid + it * 256;
            int r = idx >> 3, c4 = idx & 7;
            int ks = c4 >> 1, h = c4 & 1;
            uint32_t* s = base + (128 + r) * PITCH + ks * 8 + h;
            s[0] = tf32u(br[it].x); s[2] = tf32u(br[it].y);
            s[4] = tf32u(br[it].z); s[6] = tf32u(br[it].w);
        }
    };

    loadA(0); loadB(0);
    stsAll(0);
    __syncthreads();

    for (int cc = 0; cc < INDIM / 32; cc++) {
        const int cur = cc & 1;
        const bool hasNext = (cc + 1 < INDIM / 32);
        if (hasNext) { loadA((cc + 1) * 32); loadB((cc + 1) * 32); }

        const uint32_t* base = sm1 + cur * (192 * PITCH);
        #pragma unroll
        for (int ks = 0; ks < 4; ks++) {
            uint32_t bfr[4][2];
            #pragma unroll
            for (int nt = 0; nt < 4; nt++) {
                uint2 t = *reinterpret_cast<const uint2*>(
                    base + (128 + wc * 32 + nt * 8 + gid) * PITCH + ks * 8 + tig * 2);
                bfr[nt][0] = t.x; bfr[nt][1] = t.y;
            }
            uint32_t afr[2][4];
            #pragma unroll
            for (int mt = 0; mt < 2; mt++) {
                int r0 = wr * 32 + mt * 16 + gid;
                uint2 t0 = *reinterpret_cast<const uint2*>(base + r0 * PITCH + ks * 8 + tig * 2);
                uint2 t1 = *reinterpret_cast<const uint2*>(base + (r0 + 8) * PITCH + ks * 8 + tig * 2);
                afr[mt][0] = t0.x; afr[mt][2] = t0.y;
                afr[mt][1] = t1.x; afr[mt][3] = t1.y;
            }
            #pragma unroll
            for (int mt = 0; mt < 2; mt++)
                #pragma unroll
                for (int nt = 0; nt < 4; nt++)
                    mma_tf32(c[mt][nt], afr[mt], bfr[nt]);
        }
        if (hasNext) {
            stsAll(cur ^ 1);
            __syncthreads();
        }
    }

    // Epilogue: bias + relu, write transposed HT[b][f][m]
    const int batch = mBase >> 8;                 // 128-tile never straddles batch
    float* dst = HT + (size_t)batch * OUTDIM * N_;
    const int mloc = (mBase & 255) + wr * 32;
    #pragma unroll
    for (int mt = 0; mt < 2; mt++) {
        int m0 = mloc + mt * 16 + gid;
        #pragma unroll
        for (int nt = 0; nt < 4; nt++) {
            int f0 = fBase + wc * 32 + nt * 8 + tig * 2;
            float b0 = bias[f0], b1 = bias[f0 + 1];
            dst[(size_t)f0 * N_ + m0]           = fmaxf(c[mt][nt][0] + b0, 0.0f);
            dst[(size_t)(f0 + 1) * N_ + m0]     = fmaxf(c[mt][nt][1] + b1, 0.0f);
            dst[(size_t)f0 * N_ + m0 + 8]       = fmaxf(c[mt][nt][2] + b0, 0.0f);
            dst[(size_t)(f0 + 1) * N_ + m0 + 8] = fmaxf(c[mt][nt][3] + b1, 0.0f);
        }
    }
}

// ---------------------------------------------------------------------------
// Stage 2: out[b,n,k*64+d] = sum_m adj[b,k,n,m] * HT[b][k*64+d][m]
// CTA 128(n) x 64(d), 8 warps (4 n x 2 d), warp tile 32x32. m chunks of 32.
// Double-buffered smem: buffer = 192 rows (A: 0..127, B: 128..191) x PITCH.
// (unchanged from measured 59.9us version)
// ---------------------------------------------------------------------------
#define S2_DYN (2 * 192 * PITCH * 4)
__global__ __launch_bounds__(256) void s2_aggregate_mma(
    const float* __restrict__ adj, const float* __restrict__ HT,
    float* __restrict__ out)
{
    extern __shared__ uint32_t sm2[];

    const int tid = threadIdx.x;
    const int warpId = tid >> 5, lid = tid & 31;
    const int gid = lid >> 2, tig = lid & 3;
    const int wr = warpId & 3;            // n: 4 warps * 32
    const int wc = warpId >> 2;           // d: 2 warps * 32
    const int nBase = blockIdx.x * 128;
    const int kslot = blockIdx.y;
    const int bIdx  = blockIdx.z;

    const float* A  = adj + (size_t)(bIdx * KSLOT + kslot) * N_ * N_;
    const float* Bp = HT + ((size_t)bIdx * OUTDIM + kslot * DKDIM) * N_;

    float c[2][4][4];
    #pragma unroll
    for (int mt = 0; mt < 2; mt++)
        #pragma unroll
        for (int nt = 0; nt < 4; nt++)
            #pragma unroll
            for (int i = 0; i < 4; i++) c[mt][nt][i] = 0.0f;

    float4 ar[4], br[2];

    auto loadA = [&](int m0) {
        #pragma unroll
        for (int it = 0; it < 4; it++) {
            int idx = tid + it * 256;
            int r = idx >> 3, c4 = idx & 7;
            ar[it] = *reinterpret_cast<const float4*>(A + (size_t)(nBase + r) * N_ + m0 + c4 * 4);
        }
    };
    auto loadB = [&](int m0) {
        #pragma unroll
        for (int it = 0; it < 2; it++) {
            int idx = tid + it * 256;
            int r = idx >> 3, c4 = idx & 7;
            br[it] = *reinterpret_cast<const float4*>(Bp + (size_t)r * N_ + m0 + c4 * 4);
        }
    };
    auto stsAll = [&](int buf) {
        uint32_t* base = sm2 + buf * (192 * PITCH);
        #pragma unroll
        for (int it = 0; it < 4; it++) {
            int idx = tid + it * 256;
            int r = idx >> 3, c4 = idx & 7;
            int ks = c4 >> 1, h = c4 & 1;
            uint32_t* s = base + r * PITCH + ks * 8 + h;
            s[0] = tf32u(ar[it].x); s[2] = tf32u(ar[it].y);
            s[4] = tf32u(ar[it].z); s[6] = tf32u(ar[it].w);
        }
        #pragma unroll
        for (int it = 0; it < 2; it++) {
            int idx = tid + it * 256;
            int r = idx >> 3, c4 = idx & 7;
            int ks = c4 >> 1, h = c4 & 1;
            uint32_t* s = base + (128 + r) * PITCH + ks * 8 + h;
            s[0] = tf32u(br[it].x); s[2] = tf32u(br[it].y);
            s[4] = tf32u(br[it].z); s[6] = tf32u(br[it].w);
        }
    };

    loadA(0); loadB(0);
    stsAll(0);
    __syncthreads();

    for (int cc = 0; cc < N_ / 32; cc++) {
        const int cur = cc & 1;
        const bool hasNext = (cc + 1 < N_ / 32);
        if (hasNext) { loadA((cc + 1) * 32); loadB((cc + 1) * 32); }

        const uint32_t* base = sm2 + cur * (192 * PITCH);
        #pragma unroll
        for (int ks = 0; ks < 4; ks++) {
            uint32_t bfr[4][2];
            #pragma unroll
            for (int nt = 0; nt < 4; nt++) {
                uint2 t = *reinterpret_cast<const uint2*>(
                    base + (128 + wc * 32 + nt * 8 + gid) * PITCH + ks * 8 + tig * 2);
                bfr[nt][0] = t.x; bfr[nt][1] = t.y;
            }
            uint32_t afr[2][4];
            #pragma unroll
            for (int mt = 0; mt < 2; mt++) {
                int r0 = wr * 32 + mt * 16 + gid;
                uint2 t0 = *reinterpret_cast<const uint2*>(base + r0 * PITCH + ks * 8 + tig * 2);
                uint2 t1 = *reinterpret_cast<const uint2*>(base + (r0 + 8) * PITCH + ks * 8 + tig * 2);
                afr[mt][0] = t0.x; afr[mt][2] = t0.y;
                afr[mt][1] = t1.x; afr[mt][3] = t1.y;
            }
            #pragma unroll
            for (int mt = 0; mt < 2; mt++)
                #pragma unroll
                for (int nt = 0; nt < 4; nt++)
                    mma_tf32(c[mt][nt], afr[mt], bfr[nt]);
        }
        if (hasNext) {
            stsAll(cur ^ 1);
            __syncthreads();
        }
    }

    // Epilogue: out[b][n][kslot*64 + d]
    float* dst = out + (size_t)bIdx * N_ * OUTDIM + kslot * DKDIM;
    #pragma unroll
    for (int mt = 0; mt < 2; mt++) {
        int n0 = nBase + wr * 32 + mt * 16 + gid;
        #pragma unroll
        for (int nt = 0; nt < 4; nt++) {
            int d0 = wc * 32 + nt * 8 + tig * 2;
            float2 v0 = make_float2(c[mt][nt][0], c[mt][nt][1]);
            float2 v1 = make_float2(c[mt][nt][2], c[mt][nt][3]);
            *reinterpret_cast<float2*>(dst + (size_t)n0 * OUTDIM + d0)       = v0;
            *reinterpret_cast<float2*>(dst + (size_t)(n0 + 8) * OUTDIM + d0) = v1;
        }
    }
}

// ---------------------------------------------------------------------------
extern "C" void kernel_launch(void* const* d_in, const int* in_sizes, int n_in,
                              void* d_out, int out_size)
{
    const float* node_feats = (const float*)d_in[0];  // (64,256,512)
    const float* adj        = (const float*)d_in[1];  // (64,8,256,256)
    const float* weight     = (const float*)d_in[2];  // (512,512)
    const float* bias       = (const float*)d_in[3];  // (512,)
    float* out = (float*)d_out;

    float *HT, *WT;
    cudaGetSymbolAddress((void**)&HT, g_ht);
    cudaGetSymbolAddress((void**)&WT, g_wt);

    cudaFuncSetAttribute(s1_linear_mma, cudaFuncAttributeMaxDynamicSharedMemorySize, S1_DYN);
    cudaFuncSetAttribute(s2_aggregate_mma, cudaFuncAttributeMaxDynamicSharedMemorySize, S2_DYN);

    wt_kernel<<<dim3(OUTDIM / 32, INDIM / 32), dim3(32, 8)>>>(weight, WT);
    s1_linear_mma<<<dim3(OUTDIM / 64, (B_ * N_) / 128), 256, S1_DYN>>>(node_feats, WT, bias, HT);
    s2_aggregate_mma<<<dim3(N_ / 128, KSLOT, B_), 256, S2_DYN>>>(adj, HT, out);
}

// round 7
// speedup vs baseline: 1.7832x; 1.4133x over previous
#include <cuda_runtime.h>
#include <cstdint>

#define B_     64
#define N_     256
#define INDIM  512
#define OUTDIM 512
#define KSLOT  8
#define DKDIM  64

// Scratch: H^T [b][feature][m] and W^T [out][in]
__device__ float g_ht[(size_t)B_ * OUTDIM * N_];
__device__ float g_wt[OUTDIM * INDIM];

// ---------------------------------------------------------------------------
__device__ __forceinline__ uint32_t tf32u(float x) {
    uint32_t r; asm("cvt.rna.tf32.f32 %0, %1;" : "=r"(r) : "f"(x)); return r;
}

__device__ __forceinline__ void mma_tf32(float c[4], const uint32_t a[4], const uint32_t b[2]) {
    asm volatile(
        "mma.sync.aligned.m16n8k8.row.col.f32.tf32.tf32.f32 "
        "{%0,%1,%2,%3}, {%4,%5,%6,%7}, {%8,%9}, {%0,%1,%2,%3};"
        : "+f"(c[0]), "+f"(c[1]), "+f"(c[2]), "+f"(c[3])
        : "r"(a[0]), "r"(a[1]), "r"(a[2]), "r"(a[3]), "r"(b[0]), "r"(b[1]));
}

__device__ __forceinline__ uint32_t smem_u32(const void* p) {
    uint32_t a;
    asm("{ .reg .u64 t; cvta.to.shared.u64 t, %1; cvt.u32.u64 %0, t; }" : "=r"(a) : "l"(p));
    return a;
}

#define CP16(dst_u32, src_ptr) \
    asm volatile("cp.async.cg.shared.global [%0], [%1], 16;" :: "r"(dst_u32), "l"(src_ptr))
#define CP_COMMIT() asm volatile("cp.async.commit_group;" ::: "memory")
#define CP_WAIT0()  asm volatile("cp.async.wait_group 0;" ::: "memory")

// Plain k-major smem: row pitch 36 floats (144 B).
// Fragment LDS.32 bank = (4*gid + tig + const) mod 32 -> perfect permutation,
// 1-phase conflict-free. 16B global chunks land contiguous (cp.async-friendly).
#define PITCH 36
#define BUFROWS 192                       // A: rows 0..127, B: rows 128..191
#define BUFSZ  (BUFROWS * PITCH)          // floats per buffer

// ---------------------------------------------------------------------------
// Kernel 0: W^T  (Wt[n][k] = W[k][n])
// ---------------------------------------------------------------------------
__global__ __launch_bounds__(256) void wt_kernel(const float* __restrict__ W,
                                                 float* __restrict__ Wt) {
    __shared__ float t[32][33];
    const int bx = blockIdx.x * 32;   // out (n)
    const int by = blockIdx.y * 32;   // in  (k)
    #pragma unroll
    for (int i = 0; i < 4; i++)
        t[threadIdx.y + i * 8][threadIdx.x] = W[(size_t)(by + threadIdx.y + i * 8) * OUTDIM + bx + threadIdx.x];
    __syncthreads();
    #pragma unroll
    for (int i = 0; i < 4; i++)
        Wt[(size_t)(bx + threadIdx.y + i * 8) * INDIM + by + threadIdx.x] = t[threadIdx.x][threadIdx.y + i * 8];
}

// ---------------------------------------------------------------------------
// Shared mainloop shape: CTA = 128 rows(A) x 64 cols(B), 8 warps (4 x 2),
// warp tile 32x32, k-chunks of 32, cp.async double-buffer.
// ---------------------------------------------------------------------------

// Fragment compute over one resident chunk buffer.
template <int NT>
__device__ __forceinline__ void chunk_mma(
    const float* __restrict__ Sf, float c[2][NT][4],
    int wr, int wc, int gid, int tig)
{
    #pragma unroll
    for (int ks = 0; ks < 4; ks++) {
        const int kc = ks * 8 + tig;
        uint32_t bfr[NT][2];
        #pragma unroll
        for (int nt = 0; nt < NT; nt++) {
            const int row = 128 + wc * 32 + nt * 8 + gid;
            bfr[nt][0] = tf32u(Sf[row * PITCH + kc]);
            bfr[nt][1] = tf32u(Sf[row * PITCH + kc + 4]);
        }
        uint32_t afr[2][4];
        #pragma unroll
        for (int mt = 0; mt < 2; mt++) {
            const int r0 = wr * 32 + mt * 16 + gid;
            afr[mt][0] = tf32u(Sf[r0 * PITCH + kc]);
            afr[mt][1] = tf32u(Sf[(r0 + 8) * PITCH + kc]);
            afr[mt][2] = tf32u(Sf[r0 * PITCH + kc + 4]);
            afr[mt][3] = tf32u(Sf[(r0 + 8) * PITCH + kc + 4]);
        }
        #pragma unroll
        for (int mt = 0; mt < 2; mt++)
            #pragma unroll
            for (int nt = 0; nt < NT; nt++)
                mma_tf32(c[mt][nt], afr[mt], bfr[nt]);
    }
}

// ---------------------------------------------------------------------------
// Stage 1: HT[b][f][m] = relu( X @ W + bias )
// A = X rows (m), B = Wt rows (f). 16 k-chunks. Grid (8, 128).
// ---------------------------------------------------------------------------
#define S_DYN (2 * BUFSZ * 4)
__global__ __launch_bounds__(256) void s1_linear_mma(
    const float* __restrict__ X, const float* __restrict__ Wt,
    const float* __restrict__ bias, float* __restrict__ HT)
{
    extern __shared__ float smf[];
    const uint32_t sb = smem_u32(smf);

    const int tid = threadIdx.x;
    const int warpId = tid >> 5, lid = tid & 31;
    const int gid = lid >> 2, tig = lid & 3;
    const int wr = warpId & 3;            // m: 4 warps * 32
    const int wc = warpId >> 2;           // f: 2 warps * 32
    const int mBase = blockIdx.y * 128;
    const int fBase = blockIdx.x * 64;

    // cp.async load of chunk k0 into buffer buf
    auto issue = [&](int k0, int buf) {
        const uint32_t base = sb + buf * (BUFSZ * 4);
        #pragma unroll
        for (int it = 0; it < 4; it++) {          // A: 1024 chunks of 16B
            int idx = tid + it * 256;
            int r = idx >> 3, c4 = idx & 7;
            CP16(base + (uint32_t)(r * PITCH + c4 * 4) * 4,
                 X + (size_t)(mBase + r) * INDIM + k0 + c4 * 4);
        }
        #pragma unroll
        for (int it = 0; it < 2; it++) {          // B: 512 chunks
            int idx = tid + it * 256;
            int r = idx >> 3, c4 = idx & 7;
            CP16(base + (uint32_t)((128 + r) * PITCH + c4 * 4) * 4,
                 Wt + (size_t)(fBase + r) * INDIM + k0 + c4 * 4);
        }
        CP_COMMIT();
    };

    float c[2][4][4];
    #pragma unroll
    for (int mt = 0; mt < 2; mt++)
        #pragma unroll
        for (int nt = 0; nt < 4; nt++)
            #pragma unroll
            for (int i = 0; i < 4; i++) c[mt][nt][i] = 0.0f;

    issue(0, 0);
    const int NCHUNK = INDIM / 32;                // 16
    for (int cc = 0; cc < NCHUNK; cc++) {
        CP_WAIT0();
        __syncthreads();
        if (cc + 1 < NCHUNK) issue((cc + 1) * 32, (cc + 1) & 1);
        chunk_mma<4>(smf + (cc & 1) * BUFSZ, c, wr, wc, gid, tig);
    }

    // Epilogue: bias + relu, write transposed HT[b][f][m]
    const int batch = mBase >> 8;                 // 128-tile never straddles batch
    float* dst = HT + (size_t)batch * OUTDIM * N_;
    const int mloc = (mBase & 255) + wr * 32;
    #pragma unroll
    for (int mt = 0; mt < 2; mt++) {
        int m0 = mloc + mt * 16 + gid;
        #pragma unroll
        for (int nt = 0; nt < 4; nt++) {
            int f0 = fBase + wc * 32 + nt * 8 + tig * 2;
            float b0 = bias[f0], b1 = bias[f0 + 1];
            dst[(size_t)f0 * N_ + m0]           = fmaxf(c[mt][nt][0] + b0, 0.0f);
            dst[(size_t)(f0 + 1) * N_ + m0]     = fmaxf(c[mt][nt][1] + b1, 0.0f);
            dst[(size_t)f0 * N_ + m0 + 8]       = fmaxf(c[mt][nt][2] + b0, 0.0f);
            dst[(size_t)(f0 + 1) * N_ + m0 + 8] = fmaxf(c[mt][nt][3] + b1, 0.0f);
        }
    }
}

// ---------------------------------------------------------------------------
// Stage 2: out[b,n,k*64+d] = sum_m adj[b,k,n,m] * HT[b][k*64+d][m]
// A = adj rows (n), B = HT rows (d). 8 m-chunks. Grid (2, 8, 64).
// ---------------------------------------------------------------------------
__global__ __launch_bounds__(256) void s2_aggregate_mma(
    const float* __restrict__ adj, const float* __restrict__ HT,
    float* __restrict__ out)
{
    extern __shared__ float smf2[];
    const uint32_t sb = smem_u32(smf2);

    const int tid = threadIdx.x;
    const int warpId = tid >> 5, lid = tid & 31;
    const int gid = lid >> 2, tig = lid & 3;
    const int wr = warpId & 3;            // n: 4 warps * 32
    const int wc = warpId >> 2;           // d: 2 warps * 32
    const int nBase = blockIdx.x * 128;
    const int kslot = blockIdx.y;
    const int bIdx  = blockIdx.z;

    const float* A  = adj + (size_t)(bIdx * KSLOT + kslot) * N_ * N_;
    const float* Bp = HT + ((size_t)bIdx * OUTDIM + kslot * DKDIM) * N_;

    auto issue = [&](int m0, int buf) {
        const uint32_t base = sb + buf * (BUFSZ * 4);
        #pragma unroll
        for (int it = 0; it < 4; it++) {
            int idx = tid + it * 256;
            int r = idx >> 3, c4 = idx & 7;
            CP16(base + (uint32_t)(r * PITCH + c4 * 4) * 4,
                 A + (size_t)(nBase + r) * N_ + m0 + c4 * 4);
        }
        #pragma unroll
        for (int it = 0; it < 2; it++) {
            int idx = tid + it * 256;
            int r = idx >> 3, c4 = idx & 7;
            CP16(base + (uint32_t)((128 + r) * PITCH + c4 * 4) * 4,
                 Bp + (size_t)r * N_ + m0 + c4 * 4);
        }
        CP_COMMIT();
    };

    float c[2][4][4];
    #pragma unroll
    for (int mt = 0; mt < 2; mt++)
        #pragma unroll
        for (int nt = 0; nt < 4; nt++)
            #pragma unroll
            for (int i = 0; i < 4; i++) c[mt][nt][i] = 0.0f;

    issue(0, 0);
    const int NCHUNK = N_ / 32;                   // 8
    for (int cc = 0; cc < NCHUNK; cc++) {
        CP_WAIT0();
        __syncthreads();
        if (cc + 1 < NCHUNK) issue((cc + 1) * 32, (cc + 1) & 1);
        chunk_mma<4>(smf2 + (cc & 1) * BUFSZ, c, wr, wc, gid, tig);
    }

    // Epilogue: out[b][n][kslot*64 + d]
    float* dst = out + (size_t)bIdx * N_ * OUTDIM + kslot * DKDIM;
    #pragma unroll
    for (int mt = 0; mt < 2; mt++) {
        int n0 = nBase + wr * 32 + mt * 16 + gid;
        #pragma unroll
        for (int nt = 0; nt < 4; nt++) {
            int d0 = wc * 32 + nt * 8 + tig * 2;
            float2 v0 = make_float2(c[mt][nt][0], c[mt][nt][1]);
            float2 v1 = make_float2(c[mt][nt][2], c[mt][nt][3]);
            *reinterpret_cast<float2*>(dst + (size_t)n0 * OUTDIM + d0)       = v0;
            *reinterpret_cast<float2*>(dst + (size_t)(n0 + 8) * OUTDIM + d0) = v1;
        }
    }
}

// ---------------------------------------------------------------------------
extern "C" void kernel_launch(void* const* d_in, const int* in_sizes, int n_in,
                              void* d_out, int out_size)
{
    const float* node_feats = (const float*)d_in[0];  // (64,256,512)
    const float* adj        = (const float*)d_in[1];  // (64,8,256,256)
    const float* weight     = (const float*)d_in[2];  // (512,512)
    const float* bias       = (const float*)d_in[3];  // (512,)
    float* out = (float*)d_out;

    float *HT, *WT;
    cudaGetSymbolAddress((void**)&HT, g_ht);
    cudaGetSymbolAddress((void**)&WT, g_wt);

    cudaFuncSetAttribute(s1_linear_mma, cudaFuncAttributeMaxDynamicSharedMemorySize, S_DYN);
    cudaFuncSetAttribute(s2_aggregate_mma, cudaFuncAttributeMaxDynamicSharedMemorySize, S_DYN);

    wt_kernel<<<dim3(OUTDIM / 32, INDIM / 32), dim3(32, 8)>>>(weight, WT);
    s1_linear_mma<<<dim3(OUTDIM / 64, (B_ * N_) / 128), 256, S_DYN>>>(node_feats, WT, bias, HT);
    s2_aggregate_mma<<<dim3(N_ / 128, KSLOT, B_), 256, S_DYN>>>(adj, HT, out);
}

// round 8
// speedup vs baseline: 1.9795x; 1.1101x over previous
#include <cuda_runtime.h>
#include <cstdint>

#define B_     64
#define N_     256
#define INDIM  512
#define OUTDIM 512
#define KSLOT  8
#define DKDIM  64

// Scratch: H^T [b][feature][m] and W^T [out][in]
__device__ float g_ht[(size_t)B_ * OUTDIM * N_];
__device__ float g_wt[OUTDIM * INDIM];

// ---------------------------------------------------------------------------
__device__ __forceinline__ uint32_t tf32u(float x) {
    uint32_t r; asm("cvt.rna.tf32.f32 %0, %1;" : "=r"(r) : "f"(x)); return r;
}

__device__ __forceinline__ void mma_tf32(float c[4], const uint32_t a[4], const uint32_t b[2]) {
    asm volatile(
        "mma.sync.aligned.m16n8k8.row.col.f32.tf32.tf32.f32 "
        "{%0,%1,%2,%3}, {%4,%5,%6,%7}, {%8,%9}, {%0,%1,%2,%3};"
        : "+f"(c[0]), "+f"(c[1]), "+f"(c[2]), "+f"(c[3])
        : "r"(a[0]), "r"(a[1]), "r"(a[2]), "r"(a[3]), "r"(b[0]), "r"(b[1]));
}

__device__ __forceinline__ uint32_t smem_u32(const void* p) {
    uint32_t a;
    asm("{ .reg .u64 t; cvta.to.shared.u64 t, %1; cvt.u32.u64 %0, t; }" : "=r"(a) : "l"(p));
    return a;
}

#define CP16(dst_u32, src_ptr) \
    asm volatile("cp.async.cg.shared.global [%0], [%1], 16;" :: "r"(dst_u32), "l"(src_ptr))
#define CP_COMMIT() asm volatile("cp.async.commit_group;" ::: "memory")
#define CP_WAIT0()  asm volatile("cp.async.wait_group 0;" ::: "memory")

// Plain k-major smem: row pitch 36 floats (144 B).
// Fragment LDS.32 bank = (4*gid + tig + const) mod 32 -> perfect permutation,
// 1-phase conflict-free. 16B global chunks land contiguous (cp.async-friendly).
#define PITCH 36
#define BUFROWS 192                       // A: rows 0..127, B: rows 128..191
#define BUFSZ  (BUFROWS * PITCH)          // floats per buffer

// ---------------------------------------------------------------------------
// Kernel 0: W^T  (Wt[n][k] = W[k][n])
// ---------------------------------------------------------------------------
__global__ __launch_bounds__(256) void wt_kernel(const float* __restrict__ W,
                                                 float* __restrict__ Wt) {
    __shared__ float t[32][33];
    const int bx = blockIdx.x * 32;   // out (n)
    const int by = blockIdx.y * 32;   // in  (k)
    #pragma unroll
    for (int i = 0; i < 4; i++)
        t[threadIdx.y + i * 8][threadIdx.x] = W[(size_t)(by + threadIdx.y + i * 8) * OUTDIM + bx + threadIdx.x];
    __syncthreads();
    #pragma unroll
    for (int i = 0; i < 4; i++)
        Wt[(size_t)(bx + threadIdx.y + i * 8) * INDIM + by + threadIdx.x] = t[threadIdx.x][threadIdx.y + i * 8];
}

// ---------------------------------------------------------------------------
// Mainloop shape: CTA = 128 rows(A) x 64 cols(B), 4 warps (2 wr x 2 wc),
// warp tile 64(m) x 32(n): 4 mt x 4 nt. k-chunks of 32, cp.async dbl-buffer.
// Fragment bytes/MAC = 0.1875 (vs 0.25 at 32x32 warp tile).
// ---------------------------------------------------------------------------
template <int MT, int NT>
__device__ __forceinline__ void chunk_mma(
    const float* __restrict__ Sf, float c[MT][NT][4],
    int wr, int wc, int gid, int tig)
{
    #pragma unroll
    for (int ks = 0; ks < 4; ks++) {
        const int kc = ks * 8 + tig;
        uint32_t bfr[NT][2];
        #pragma unroll
        for (int nt = 0; nt < NT; nt++) {
            const int row = 128 + wc * 32 + nt * 8 + gid;
            bfr[nt][0] = tf32u(Sf[row * PITCH + kc]);
            bfr[nt][1] = tf32u(Sf[row * PITCH + kc + 4]);
        }
        uint32_t afr[MT][4];
        #pragma unroll
        for (int mt = 0; mt < MT; mt++) {
            const int r0 = wr * (MT * 16) + mt * 16 + gid;
            afr[mt][0] = tf32u(Sf[r0 * PITCH + kc]);
            afr[mt][1] = tf32u(Sf[(r0 + 8) * PITCH + kc]);
            afr[mt][2] = tf32u(Sf[r0 * PITCH + kc + 4]);
            afr[mt][3] = tf32u(Sf[(r0 + 8) * PITCH + kc + 4]);
        }
        #pragma unroll
        for (int mt = 0; mt < MT; mt++)
            #pragma unroll
            for (int nt = 0; nt < NT; nt++)
                mma_tf32(c[mt][nt], afr[mt], bfr[nt]);
    }
}

// ---------------------------------------------------------------------------
// Stage 1: HT[b][f][m] = relu( X @ W + bias )
// A = X rows (m), B = Wt rows (f). 16 k-chunks. Grid (8, 128), 128 threads.
// ---------------------------------------------------------------------------
#define S_DYN (2 * BUFSZ * 4)
__global__ __launch_bounds__(128) void s1_linear_mma(
    const float* __restrict__ X, const float* __restrict__ Wt,
    const float* __restrict__ bias, float* __restrict__ HT)
{
    extern __shared__ float smf[];
    const uint32_t sb = smem_u32(smf);

    const int tid = threadIdx.x;
    const int warpId = tid >> 5, lid = tid & 31;
    const int gid = lid >> 2, tig = lid & 3;
    const int wr = warpId & 1;            // m: 2 warps * 64
    const int wc = warpId >> 1;           // f: 2 warps * 32
    const int mBase = blockIdx.y * 128;
    const int fBase = blockIdx.x * 64;

    // cp.async load of chunk k0 into buffer buf (128 threads)
    auto issue = [&](int k0, int buf) {
        const uint32_t base = sb + buf * (BUFSZ * 4);
        #pragma unroll
        for (int it = 0; it < 8; it++) {          // A: 1024 chunks of 16B
            int idx = tid + it * 128;
            int r = idx >> 3, c4 = idx & 7;
            CP16(base + (uint32_t)(r * PITCH + c4 * 4) * 4,
                 X + (size_t)(mBase + r) * INDIM + k0 + c4 * 4);
        }
        #pragma unroll
        for (int it = 0; it < 4; it++) {          // B: 512 chunks
            int idx = tid + it * 128;
            int r = idx >> 3, c4 = idx & 7;
            CP16(base + (uint32_t)((128 + r) * PITCH + c4 * 4) * 4,
                 Wt + (size_t)(fBase + r) * INDIM + k0 + c4 * 4);
        }
        CP_COMMIT();
    };

    float c[4][4][4];
    #pragma unroll
    for (int mt = 0; mt < 4; mt++)
        #pragma unroll
        for (int nt = 0; nt < 4; nt++)
            #pragma unroll
            for (int i = 0; i < 4; i++) c[mt][nt][i] = 0.0f;

    issue(0, 0);
    const int NCHUNK = INDIM / 32;                // 16
    for (int cc = 0; cc < NCHUNK; cc++) {
        CP_WAIT0();
        __syncthreads();
        if (cc + 1 < NCHUNK) issue((cc + 1) * 32, (cc + 1) & 1);
        chunk_mma<4, 4>(smf + (cc & 1) * BUFSZ, c, wr, wc, gid, tig);
    }

    // Epilogue: bias + relu, write transposed HT[b][f][m]
    const int batch = mBase >> 8;                 // 128-tile never straddles batch
    float* dst = HT + (size_t)batch * OUTDIM * N_;
    const int mloc = (mBase & 255) + wr * 64;
    #pragma unroll
    for (int mt = 0; mt < 4; mt++) {
        int m0 = mloc + mt * 16 + gid;
        #pragma unroll
        for (int nt = 0; nt < 4; nt++) {
            int f0 = fBase + wc * 32 + nt * 8 + tig * 2;
            float b0 = bias[f0], b1 = bias[f0 + 1];
            dst[(size_t)f0 * N_ + m0]           = fmaxf(c[mt][nt][0] + b0, 0.0f);
            dst[(size_t)(f0 + 1) * N_ + m0]     = fmaxf(c[mt][nt][1] + b1, 0.0f);
            dst[(size_t)f0 * N_ + m0 + 8]       = fmaxf(c[mt][nt][2] + b0, 0.0f);
            dst[(size_t)(f0 + 1) * N_ + m0 + 8] = fmaxf(c[mt][nt][3] + b1, 0.0f);
        }
    }
}

// ---------------------------------------------------------------------------
// Stage 2: out[b,n,k*64+d] = sum_m adj[b,k,n,m] * HT[b][k*64+d][m]
// A = adj rows (n), B = HT rows (d). 8 m-chunks. Grid (2, 8, 64), 128 thr.
// ---------------------------------------------------------------------------
__global__ __launch_bounds__(128) void s2_aggregate_mma(
    const float* __restrict__ adj, const float* __restrict__ HT,
    float* __restrict__ out)
{
    extern __shared__ float smf2[];
    const uint32_t sb = smem_u32(smf2);

    const int tid = threadIdx.x;
    const int warpId = tid >> 5, lid = tid & 31;
    const int gid = lid >> 2, tig = lid & 3;
    const int wr = warpId & 1;            // n: 2 warps * 64
    const int wc = warpId >> 1;           // d: 2 warps * 32
    const int nBase = blockIdx.x * 128;
    const int kslot = blockIdx.y;
    const int bIdx  = blockIdx.z;

    const float* A  = adj + (size_t)(bIdx * KSLOT + kslot) * N_ * N_;
    const float* Bp = HT + ((size_t)bIdx * OUTDIM + kslot * DKDIM) * N_;

    auto issue = [&](int m0, int buf) {
        const uint32_t base = sb + buf * (BUFSZ * 4);
        #pragma unroll
        for (int it = 0; it < 8; it++) {
            int idx = tid + it * 128;
            int r = idx >> 3, c4 = idx & 7;
            CP16(base + (uint32_t)(r * PITCH + c4 * 4) * 4,
                 A + (size_t)(nBase + r) * N_ + m0 + c4 * 4);
        }
        #pragma unroll
        for (int it = 0; it < 4; it++) {
            int idx = tid + it * 128;
            int r = idx >> 3, c4 = idx & 7;
            CP16(base + (uint32_t)((128 + r) * PITCH + c4 * 4) * 4,
                 Bp + (size_t)r * N_ + m0 + c4 * 4);
        }
        CP_COMMIT();
    };

    float c[4][4][4];
    #pragma unroll
    for (int mt = 0; mt < 4; mt++)
        #pragma unroll
        for (int nt = 0; nt < 4; nt++)
            #pragma unroll
            for (int i = 0; i < 4; i++) c[mt][nt][i] = 0.0f;

    issue(0, 0);
    const int NCHUNK = N_ / 32;                   // 8
    for (int cc = 0; cc < NCHUNK; cc++) {
        CP_WAIT0();
        __syncthreads();
        if (cc + 1 < NCHUNK) issue((cc + 1) * 32, (cc + 1) & 1);
        chunk_mma<4, 4>(smf2 + (cc & 1) * BUFSZ, c, wr, wc, gid, tig);
    }

    // Epilogue: out[b][n][kslot*64 + d]
    float* dst = out + (size_t)bIdx * N_ * OUTDIM + kslot * DKDIM;
    #pragma unroll
    for (int mt = 0; mt < 4; mt++) {
        int n0 = nBase + wr * 64 + mt * 16 + gid;
        #pragma unroll
        for (int nt = 0; nt < 4; nt++) {
            int d0 = wc * 32 + nt * 8 + tig * 2;
            float2 v0 = make_float2(c[mt][nt][0], c[mt][nt][1]);
            float2 v1 = make_float2(c[mt][nt][2], c[mt][nt][3]);
            *reinterpret_cast<float2*>(dst + (size_t)n0 * OUTDIM + d0)       = v0;
            *reinterpret_cast<float2*>(dst + (size_t)(n0 + 8) * OUTDIM + d0) = v1;
        }
    }
}

// ---------------------------------------------------------------------------
extern "C" void kernel_launch(void* const* d_in, const int* in_sizes, int n_in,
                              void* d_out, int out_size)
{
    const float* node_feats = (const float*)d_in[0];  // (64,256,512)
    const float* adj        = (const float*)d_in[1];  // (64,8,256,256)
    const float* weight     = (const float*)d_in[2];  // (512,512)
    const float* bias       = (const float*)d_in[3];  // (512,)
    float* out = (float*)d_out;

    float *HT, *WT;
    cudaGetSymbolAddress((void**)&HT, g_ht);
    cudaGetSymbolAddress((void**)&WT, g_wt);

    cudaFuncSetAttribute(s1_linear_mma, cudaFuncAttributeMaxDynamicSharedMemorySize, S_DYN);
    cudaFuncSetAttribute(s2_aggregate_mma, cudaFuncAttributeMaxDynamicSharedMemorySize, S_DYN);

    wt_kernel<<<dim3(OUTDIM / 32, INDIM / 32), dim3(32, 8)>>>(weight, WT);
    s1_linear_mma<<<dim3(OUTDIM / 64, (B_ * N_) / 128), 128, S_DYN>>>(node_feats, WT, bias, HT);
    s2_aggregate_mma<<<dim3(N_ / 128, KSLOT, B_), 128, S_DYN>>>(adj, HT, out);
}